// round 16
// baseline (speedup 1.0000x reference)
#include <cuda_runtime.h>
#include <cstdint>

#define BB   8
#define CC   256
#define CQ   32
#define NN   16384
#define EPSV 1e-6f

// ---------------- scratch (device globals) ---------------------------------
__device__ __align__(16) uint32_t g_WtF[4 * 16 * 32 * 4];   // bf16 A-frags; wo 0-1 = Wq, 2-3 = Wk
__device__ float g_mpT[BB * CC * CQ];                       // (Kn @ x^T)^T : [b][c][m]
__device__ float g_S[BB * CQ];                              // sum_n Kn
__device__ float g_xsum[BB * CC];                           // sum_n x
__device__ __align__(16) uint32_t g_mfrag[BB * 16 * 2 * 32 * 4]; // matT bf16 A-frags
__device__ float g_vsum[BB * CC];                           // value_sum
__device__ __align__(16) uint4 g_qfrag[(size_t)BB * 2048 * 32]; // Qn bf16 B-frags [b][jt][lane]

// pack two fp32 -> bf16x2 (lo in bits 0-15, hi in bits 16-31)
__device__ __forceinline__ uint32_t f2bf2(float lo, float hi) {
    uint32_t r;
    asm("cvt.rn.bf16x2.f32 %0, %1, %2;" : "=r"(r) : "f"(hi), "f"(lo));
    return r;
}
__device__ __forceinline__ float bf_lo(uint32_t v) { return __uint_as_float(v << 16); }
__device__ __forceinline__ float bf_hi(uint32_t v) { return __uint_as_float(v & 0xffff0000u); }

__device__ __forceinline__ void mma_bf16(float& d0, float& d1, float& d2, float& d3,
                                         uint32_t a0, uint32_t a1, uint32_t a2, uint32_t a3,
                                         uint32_t b0, uint32_t b1) {
    asm volatile(
        "mma.sync.aligned.m16n8k16.row.col.f32.bf16.bf16.f32 "
        "{%0,%1,%2,%3},{%4,%5,%6,%7},{%8,%9},{%0,%1,%2,%3};"
        : "+f"(d0), "+f"(d1), "+f"(d2), "+f"(d3)
        : "r"(a0), "r"(a1), "r"(a2), "r"(a3), "r"(b0), "r"(b1));
}

// ---------------- kernel 0: zero accumulators + build bf16 W-fragments -----
__global__ void k_prep(const float* __restrict__ Wq, const float* __restrict__ Wk) {
    int idx = blockIdx.x * blockDim.x + threadIdx.x;      // 65536 threads
    if (idx < BB * CC * CQ) g_mpT[idx] = 0.f;
    if (idx < 8192) {
        int f    = idx & 3;           // a0..a3
        int lane = (idx >> 2) & 31;
        int kk   = (idx >> 7) & 15;
        int wo   = (idx >> 11) & 3;
        int gid = lane >> 2, tig = lane & 3;
        int o = (wo & 1) * 16 + gid + (f & 1) * 8;
        int c = kk * 16 + 2 * tig + (f >> 1) * 8;
        const float* W = (wo < 2) ? Wq : Wk;
        g_WtF[idx] = f2bf2(W[o * CC + c], W[o * CC + c + 1]);
    }
    if (idx < BB * CC) g_xsum[idx] = 0.f;
    if (idx < BB * CQ) g_S[idx] = 0.f;
}

// ---------------- kernel 1: FUSED Q+K proj + Qn frags + S + xsum + mpT ------
// block = (b, 256-j slice). Phase A: proj with 4 subtiles interleaved per warp.
// Phase B: mpT mma (x re-read, L2).
__global__ void __launch_bounds__(256)
k_fused(const float* __restrict__ x, const float* __restrict__ bq,
        const float* __restrict__ bk) {
    __shared__ uint32_t kb[32][132];     // Kn bf16x2 j-pairs: [m][jpair]
    __shared__ float qts[8 * 288];       // per-warp Qn fp32 transpose scratch

    const int tid = threadIdx.x;
    const int w = tid >> 5, lane = tid & 31, gid = lane >> 2, tig = lane & 3;
    const int b   = blockIdx.x >> 6;
    const int jsl = blockIdx.x & 63;                 // 256-j slice
    const float* xb = x + (size_t)b * CC * NN;

    const float bq0 = __ldg(&bq[gid]),      bq1 = __ldg(&bq[gid + 8]);
    const float bq2 = __ldg(&bq[gid + 16]), bq3 = __ldg(&bq[gid + 24]);
    const float bk0 = __ldg(&bk[gid]),      bk1 = __ldg(&bk[gid + 8]);
    const float bk2 = __ldg(&bk[gid + 16]), bk3 = __ldg(&bk[gid + 24]);

    const uint4* Wt = (const uint4*)g_WtF + lane;
    float* Qf = qts + w * 288;                       // [32 o][9] fp32 slice

    float S0 = 0.f, S1 = 0.f, S2 = 0.f, S3 = 0.f;

    // ================= phase A: projections, 4 subtiles interleaved ==========
    {
        const int jb = jsl * 256 + w * 8;            // tile t at jb + 64*t
        const float* xp = xb + (size_t)(2 * tig) * NN + jb + gid;

        float dq[4][2][4], dk[4][2][4];    // [tile][o-half][quad]
        #pragma unroll
        for (int t = 0; t < 4; t++)
            #pragma unroll
            for (int h = 0; h < 2; h++)
                #pragma unroll
                for (int q = 0; q < 4; q++) { dq[t][h][q] = 0.f; dk[t][h][q] = 0.f; }

        #pragma unroll 4
        for (int kk = 0; kk < 16; kk++) {
            const size_t r0 = (size_t)(16 * kk) * NN;
            uint32_t pb[4][2];
            #pragma unroll
            for (int t = 0; t < 4; t++) {
                const float* p = xp + 64 * t + r0;
                float u0 = __ldg(p);
                float u1 = __ldg(p + NN);
                float u2 = __ldg(p + 8 * NN);
                float u3 = __ldg(p + 9 * NN);
                pb[t][0] = f2bf2(u0, u1);
                pb[t][1] = f2bf2(u2, u3);
            }
            uint4 a0 = Wt[kk * 32];
            uint4 a1 = Wt[512 + kk * 32];
            uint4 a2 = Wt[1024 + kk * 32];
            uint4 a3 = Wt[1536 + kk * 32];
            #pragma unroll
            for (int t = 0; t < 4; t++) {
                mma_bf16(dq[t][0][0], dq[t][0][1], dq[t][0][2], dq[t][0][3],
                         a0.x, a0.y, a0.z, a0.w, pb[t][0], pb[t][1]);
                mma_bf16(dq[t][1][0], dq[t][1][1], dq[t][1][2], dq[t][1][3],
                         a1.x, a1.y, a1.z, a1.w, pb[t][0], pb[t][1]);
                mma_bf16(dk[t][0][0], dk[t][0][1], dk[t][0][2], dk[t][0][3],
                         a2.x, a2.y, a2.z, a2.w, pb[t][0], pb[t][1]);
                mma_bf16(dk[t][1][0], dk[t][1][1], dk[t][1][2], dk[t][1][3],
                         a3.x, a3.y, a3.z, a3.w, pb[t][0], pb[t][1]);
            }
        }

        // ---- per-tile epilogue (norms, S, kb, qfrag) ----
        #pragma unroll
        for (int t = 0; t < 4; t++) {
            const int jbase = jb + 64 * t;
            const int jt = jbase >> 3;

            float q00 = dq[t][0][0] + bq0, q01 = dq[t][0][1] + bq0;
            float q02 = dq[t][0][2] + bq1, q03 = dq[t][0][3] + bq1;
            float q10 = dq[t][1][0] + bq2, q11 = dq[t][1][1] + bq2;
            float q12 = dq[t][1][2] + bq3, q13 = dq[t][1][3] + bq3;
            float c00 = dk[t][0][0] + bk0, c01 = dk[t][0][1] + bk0;
            float c02 = dk[t][0][2] + bk1, c03 = dk[t][0][3] + bk1;
            float c10 = dk[t][1][0] + bk2, c11 = dk[t][1][1] + bk2;
            float c12 = dk[t][1][2] + bk3, c13 = dk[t][1][3] + bk3;

            float qe = q00*q00 + q02*q02 + q10*q10 + q12*q12;
            float qo = q01*q01 + q03*q03 + q11*q11 + q13*q13;
            float ke = c00*c00 + c02*c02 + c10*c10 + c12*c12;
            float ko = c01*c01 + c03*c03 + c11*c11 + c13*c13;
            #pragma unroll
            for (int off = 4; off <= 16; off <<= 1) {
                qe += __shfl_xor_sync(0xffffffffu, qe, off);
                qo += __shfl_xor_sync(0xffffffffu, qo, off);
                ke += __shfl_xor_sync(0xffffffffu, ke, off);
                ko += __shfl_xor_sync(0xffffffffu, ko, off);
            }
            const float rqe = rsqrtf(qe), rqo = rsqrtf(qo);
            const float rke = rsqrtf(ke), rko = rsqrtf(ko);

            float k00 = c00*rke, k01 = c01*rko, k02 = c02*rke, k03 = c03*rko;
            float k10 = c10*rke, k11 = c11*rko, k12 = c12*rke, k13 = c13*rko;
            float s0 = k00 + k01, s1 = k02 + k03, s2 = k10 + k11, s3 = k12 + k13;
            s0 += __shfl_xor_sync(0xffffffffu, s0, 1); s0 += __shfl_xor_sync(0xffffffffu, s0, 2);
            s1 += __shfl_xor_sync(0xffffffffu, s1, 1); s1 += __shfl_xor_sync(0xffffffffu, s1, 2);
            s2 += __shfl_xor_sync(0xffffffffu, s2, 1); s2 += __shfl_xor_sync(0xffffffffu, s2, 2);
            s3 += __shfl_xor_sync(0xffffffffu, s3, 1); s3 += __shfl_xor_sync(0xffffffffu, s3, 2);
            S0 += s0; S1 += s1; S2 += s2; S3 += s3;

            // Kn bf16 j-pairs -> kb  (pair index = local j / 2)
            {
                const int jp = 32 * t + 4 * w + tig;
                kb[gid][jp]      = f2bf2(k00, k01);
                kb[gid + 8][jp]  = f2bf2(k02, k03);
                kb[gid + 16][jp] = f2bf2(k10, k11);
                kb[gid + 24][jp] = f2bf2(k12, k13);
            }

            // Qn -> scratch -> bf16 B-frags -> qfrag
            const int jl = 2 * tig;
            Qf[(gid)      * 9 + jl]     = q00 * rqe;
            Qf[(gid)      * 9 + jl + 1] = q01 * rqo;
            Qf[(gid + 8)  * 9 + jl]     = q02 * rqe;
            Qf[(gid + 8)  * 9 + jl + 1] = q03 * rqo;
            Qf[(gid + 16) * 9 + jl]     = q10 * rqe;
            Qf[(gid + 16) * 9 + jl + 1] = q11 * rqo;
            Qf[(gid + 24) * 9 + jl]     = q12 * rqe;
            Qf[(gid + 24) * 9 + jl + 1] = q13 * rqo;
            __syncwarp();
            {
                uint4 Bv;
                Bv.x = f2bf2(Qf[(2 * tig)      * 9 + gid], Qf[(2 * tig + 1)  * 9 + gid]);
                Bv.y = f2bf2(Qf[(2 * tig + 8)  * 9 + gid], Qf[(2 * tig + 9)  * 9 + gid]);
                Bv.z = f2bf2(Qf[(2 * tig + 16) * 9 + gid], Qf[(2 * tig + 17) * 9 + gid]);
                Bv.w = f2bf2(Qf[(2 * tig + 24) * 9 + gid], Qf[(2 * tig + 25) * 9 + gid]);
                g_qfrag[(size_t)(b * 2048 + jt) * 32 + lane] = Bv;
            }
            __syncwarp();
        }
    }

    if (tig == 0) {
        atomicAdd(&g_S[b * CQ + gid],      S0);
        atomicAdd(&g_S[b * CQ + gid + 8],  S1);
        atomicAdd(&g_S[b * CQ + gid + 16], S2);
        atomicAdd(&g_S[b * CQ + gid + 24], S3);
    }
    __syncthreads();         // all Kn pairs visible

    // ================= phase B: mpT = x @ Kn^T over this slice (k16) ========
    float e[2][4][4];
    #pragma unroll
    for (int ct = 0; ct < 2; ct++)
        #pragma unroll
        for (int mt = 0; mt < 4; mt++)
            #pragma unroll
            for (int q = 0; q < 4; q++) e[ct][mt][q] = 0.f;
    float sx[2][2] = {{0.f, 0.f}, {0.f, 0.f}};

    #pragma unroll 4
    for (int kk = 0; kk < 16; kk++) {
        const int jg = jsl * 256 + kk * 16;
        uint32_t bb0[4], bb1[4];
        #pragma unroll
        for (int mt = 0; mt < 4; mt++) {
            bb0[mt] = kb[8 * mt + gid][8 * kk + tig];
            bb1[mt] = kb[8 * mt + gid][8 * kk + 4 + tig];
        }
        #pragma unroll
        for (int ct = 0; ct < 2; ct++) {
            const int c0 = 32 * w + 16 * ct;
            float2 v0 = *(const float2*)(xb + (size_t)(c0 + gid)     * NN + jg + 2 * tig);
            float2 v1 = *(const float2*)(xb + (size_t)(c0 + 8 + gid) * NN + jg + 2 * tig);
            float2 v2 = *(const float2*)(xb + (size_t)(c0 + gid)     * NN + jg + 8 + 2 * tig);
            float2 v3 = *(const float2*)(xb + (size_t)(c0 + 8 + gid) * NN + jg + 8 + 2 * tig);
            sx[ct][0] += v0.x + v0.y + v2.x + v2.y;
            sx[ct][1] += v1.x + v1.y + v3.x + v3.y;
            uint32_t a0 = f2bf2(v0.x, v0.y);
            uint32_t a1 = f2bf2(v1.x, v1.y);
            uint32_t a2 = f2bf2(v2.x, v2.y);
            uint32_t a3 = f2bf2(v3.x, v3.y);
            #pragma unroll
            for (int mt = 0; mt < 4; mt++)
                mma_bf16(e[ct][mt][0], e[ct][mt][1], e[ct][mt][2], e[ct][mt][3],
                         a0, a1, a2, a3, bb0[mt], bb1[mt]);
        }
    }

    #pragma unroll
    for (int ct = 0; ct < 2; ct++) {
        float v0 = sx[ct][0], v1 = sx[ct][1];
        v0 += __shfl_xor_sync(0xffffffffu, v0, 1); v0 += __shfl_xor_sync(0xffffffffu, v0, 2);
        v1 += __shfl_xor_sync(0xffffffffu, v1, 1); v1 += __shfl_xor_sync(0xffffffffu, v1, 2);
        if (tig == 0) {
            const int c0 = 32 * w + 16 * ct;
            atomicAdd(&g_xsum[b * CC + c0 + gid],     v0);
            atomicAdd(&g_xsum[b * CC + c0 + 8 + gid], v1);
        }
    }
    float* mpb = &g_mpT[b * CC * CQ];
    #pragma unroll
    for (int ct = 0; ct < 2; ct++) {
        const int c0 = 32 * w + 16 * ct;
        #pragma unroll
        for (int mt = 0; mt < 4; mt++) {
            const int m0 = mt * 8 + 2 * tig;
            atomicAdd(&mpb[(c0 + gid) * CQ + m0],         e[ct][mt][0]);
            atomicAdd(&mpb[(c0 + gid) * CQ + m0 + 1],     e[ct][mt][1]);
            atomicAdd(&mpb[(c0 + 8 + gid) * CQ + m0],     e[ct][mt][2]);
            atomicAdd(&mpb[(c0 + 8 + gid) * CQ + m0 + 1], e[ct][mt][3]);
        }
    }
}

// ---------------- kernel 2: matrix = mp @ Wv^T + bv (x) S ; vsum; fragments -
// 128 blocks. warp w = m-group (4 m), lane = (cl 0..15, ch 0..1), split-c.
__global__ void __launch_bounds__(256)
k_mat(const float* __restrict__ Wv, const float* __restrict__ bv) {
    extern __shared__ float shm[];
    float* mpT_s = shm;                 // [256 c][32 m]
    float* wv_s  = shm + CC * CQ;       // [16 cl][257]
    float* xs_s  = wv_s + 16 * 257;     // [256]
    float* S_s   = xs_s + CC;           // [32]

    const int b  = blockIdx.x >> 4;
    const int cg = (blockIdx.x & 15) * 16;
    const int tid = threadIdx.x;
    const int w = tid >> 5, lane = tid & 31;
    const int cl = lane & 15, ch = lane >> 4;

    for (int idx = tid; idx < CC * CQ; idx += 256)
        mpT_s[idx] = g_mpT[b * CC * CQ + idx];
    for (int idx = tid; idx < 16 * CC; idx += 256) {
        int l = idx >> 8, c = idx & 255;
        wv_s[l * 257 + c] = Wv[(cg + l) * CC + c];
    }
    xs_s[tid] = g_xsum[b * CC + tid];
    if (tid < 32) S_s[tid] = g_S[b * CQ + tid];
    __syncthreads();

    const int cp = cg + cl;
    const int m0 = 4 * w;
    const float bvv = __ldg(&bv[cp]);

    float acc[4];
    #pragma unroll
    for (int i = 0; i < 4; i++)
        acc[i] = (ch == 0) ? bvv * S_s[m0 + i] : 0.f;
    float vs = (ch == 0) ? (float)NN * bvv : 0.f;

    const float* wrow = &wv_s[cl * 257] + ch * 128;
    const float* xsp  = xs_s + ch * 128;
    const float* mpp  = mpT_s + (ch * 128) * CQ + m0;
    #pragma unroll 8
    for (int c = 0; c < 128; ++c) {
        float wv = wrow[c];
        vs += wv * xsp[c];
        const float4 mv = *(const float4*)(mpp + c * CQ);
        acc[0] += mv.x * wv; acc[1] += mv.y * wv;
        acc[2] += mv.z * wv; acc[3] += mv.w * wv;
    }
    #pragma unroll
    for (int i = 0; i < 4; i++)
        acc[i] += __shfl_xor_sync(0xffffffffu, acc[i], 16);
    vs += __shfl_xor_sync(0xffffffffu, vs, 16);

    if (ch == 0) {
        if (w == 0) g_vsum[b * CC + cp] = vs;
        const int ct = cp >> 4, cl16 = cp & 15;
        const int gidf = cl16 & 7, hi_row = cl16 >> 3;
        #pragma unroll
        for (int p = 0; p < 2; p++) {
            const int mg = 2 * w + p;
            const int kk = mg >> 3, tigf = mg & 3, half = (mg >> 2) & 1;
            const int elem = hi_row + 2 * half;
            g_mfrag[((((b * 16 + ct) * 2 + kk) * 32) + gidf * 4 + tigf) * 4 + elem] =
                f2bf2(acc[2 * p], acc[2 * p + 1]);
        }
    }
}

// ---------------- kernel 3: streaming epilogue, 2 j-tiles x 64 c per block --
__global__ void __launch_bounds__(256)
k_pass2(const float* __restrict__ x, const float* __restrict__ gamma,
        float* __restrict__ out) {
    const int tid = threadIdx.x;
    const int w = tid >> 5, lane = tid & 31, gid = lane >> 2, tig = lane & 3;
    const int b     = blockIdx.x >> 9;
    const int inner = blockIdx.x & 511;
    const int ch    = inner & 3;                   // c-quarter: ct 4ch..4ch+3
    const int jt0   = (inner >> 2) * 16 + w * 2;
    const int n0    = jt0 * 8;
    const float gm  = __ldg(&gamma[0]);

    const uint4* qf = g_qfrag + (size_t)(b * 2048 + jt0) * 32 + lane;
    uint4 P = __ldg(qf);          // tile 0
    uint4 R = __ldg(qf + 32);     // tile 1

    const int mt2 = 2 * tig;
    float se[8];
    #pragma unroll
    for (int i = 0; i < 4; i++) {
        se[2 * i]     = __ldg(&g_S[b * CQ + 8 * i + mt2])     + EPSV;
        se[2 * i + 1] = __ldg(&g_S[b * CQ + 8 * i + mt2 + 1]) + EPSV;
    }
    float tl0 = bf_lo(P.x) * se[0] + bf_hi(P.x) * se[1]
              + bf_lo(P.y) * se[2] + bf_hi(P.y) * se[3]
              + bf_lo(P.z) * se[4] + bf_hi(P.z) * se[5]
              + bf_lo(P.w) * se[6] + bf_hi(P.w) * se[7];
    float tl1 = bf_lo(R.x) * se[0] + bf_hi(R.x) * se[1]
              + bf_lo(R.y) * se[2] + bf_hi(R.y) * se[3]
              + bf_lo(R.z) * se[4] + bf_hi(R.z) * se[5]
              + bf_lo(R.w) * se[6] + bf_hi(R.w) * se[7];
    tl0 += __shfl_xor_sync(0xffffffffu, tl0, 1);
    tl0 += __shfl_xor_sync(0xffffffffu, tl0, 2);
    tl1 += __shfl_xor_sync(0xffffffffu, tl1, 1);
    tl1 += __shfl_xor_sync(0xffffffffu, tl1, 2);
    const float g0 = gm / (16384.f + tl0);
    const float g1 = gm / (16384.f + tl1);
    const float gt0e = __shfl_sync(0xffffffffu, g0, 8 * tig);
    const float gt0o = __shfl_sync(0xffffffffu, g0, 8 * tig + 4);
    const float gt1e = __shfl_sync(0xffffffffu, g1, 8 * tig);
    const float gt1o = __shfl_sync(0xffffffffu, g1, 8 * tig + 4);

    const float* xp = x   + (size_t)b * CC * NN + n0;
    float*       op = out + (size_t)b * CC * NN + n0;
    const uint4* mf = (const uint4*)g_mfrag + (size_t)b * 16 * 2 * 32 + lane;
    const float* vs = g_vsum + b * CC;
    const int jj = 2 * tig;
    const int ct0 = 4 * ch;

    #pragma unroll 4
    for (int ci = 0; ci < 4; ci++) {
        const int ct = ct0 + ci;
        const uint4* base = mf + ct * 64;
        uint4 A0 = __ldg(base);         // kk = 0 (m 0..15)
        uint4 A1 = __ldg(base + 32);    // kk = 1 (m 16..31)
        float e0 = 0.f, e1 = 0.f, e2 = 0.f, e3 = 0.f;
        float f0 = 0.f, f1 = 0.f, f2 = 0.f, f3 = 0.f;
        mma_bf16(e0, e1, e2, e3, A0.x, A0.y, A0.z, A0.w, P.x, P.y);
        mma_bf16(f0, f1, f2, f3, A0.x, A0.y, A0.z, A0.w, R.x, R.y);
        mma_bf16(e0, e1, e2, e3, A1.x, A1.y, A1.z, A1.w, P.z, P.w);
        mma_bf16(f0, f1, f2, f3, A1.x, A1.y, A1.z, A1.w, R.z, R.w);

        const int c1 = ct * 16 + gid;
        const int c2 = c1 + 8;
        const float v1 = __ldg(&vs[c1]), v2 = __ldg(&vs[c2]);
        float2 x10 = *(const float2*)(xp + (size_t)c1 * NN + jj);
        float2 x11 = *(const float2*)(xp + (size_t)c1 * NN + 8 + jj);
        float2 x20 = *(const float2*)(xp + (size_t)c2 * NN + jj);
        float2 x21 = *(const float2*)(xp + (size_t)c2 * NN + 8 + jj);
        float2 o10, o11, o20, o21;
        o10.x = x10.x + gt0e * (v1 + e0);
        o10.y = x10.y + gt0o * (v1 + e1);
        o11.x = x11.x + gt1e * (v1 + f0);
        o11.y = x11.y + gt1o * (v1 + f1);
        o20.x = x20.x + gt0e * (v2 + e2);
        o20.y = x20.y + gt0o * (v2 + e3);
        o21.x = x21.x + gt1e * (v2 + f2);
        o21.y = x21.y + gt1o * (v2 + f3);
        __stcs((float2*)(op + (size_t)c1 * NN + jj),     o10);
        __stcs((float2*)(op + (size_t)c1 * NN + 8 + jj), o11);
        __stcs((float2*)(op + (size_t)c2 * NN + jj),     o20);
        __stcs((float2*)(op + (size_t)c2 * NN + 8 + jj), o21);
    }
}

// ---------------- launch --------------------------------------------------
extern "C" void kernel_launch(void* const* d_in, const int* in_sizes, int n_in,
                              void* d_out, int out_size) {
    const float* x     = (const float*)d_in[0];
    const float* Wq    = (const float*)d_in[1];
    const float* bq    = (const float*)d_in[2];
    const float* Wk    = (const float*)d_in[3];
    const float* bk    = (const float*)d_in[4];
    const float* Wv    = (const float*)d_in[5];
    const float* bv    = (const float*)d_in[6];
    const float* gamma = (const float*)d_in[7];
    float* out = (float*)d_out;

    const int shMat = (CC * CQ + 16 * 257 + CC + CQ) * (int)sizeof(float);
    cudaFuncSetAttribute(k_mat, cudaFuncAttributeMaxDynamicSharedMemorySize, shMat);

    k_prep<<<256, 256>>>(Wq, Wk);
    k_fused<<<BB * 64, 256>>>(x, bq, bk);       // 512 blocks: proj(4-tile ILP, unroll 4) + mpT
    k_mat<<<BB * 16, 256, shMat>>>(Wv, bv);     // 128 blocks, split-c reduction
    k_pass2<<<BB * 512, 256>>>(x, gamma, out);  // 4096 blocks: 16 j x 64 c each
}